// round 14
// baseline (speedup 1.0000x reference)
#include <cuda_runtime.h>
#include <cuda_fp16.h>
#include <mma.h>

using namespace nvcuda;

#define NN 50000
#define NE 800000
#define DIM 64
#define NK 3
#define TR 64    // rows per GEMM block
#define CAP 64   // per-node bucket capacity (max in-degree ~45 for Poisson(16))

// ---- static scratch (no allocation allowed) ----
__device__ int   g_i64;                 // 1 if edge_index is int64, 0 if int32
__device__ int   g_cnt[NN];             // per-node fill cursor == in-degree
__device__ __align__(16) int g_col[NN * CAP];   // bucketed CSR
__device__ float g_dinv[NN];            // deg^{-1/2}
__device__ __align__(16) float g_xs[NN * DIM];  // xs = dinv * x (pre-scaled)
__device__ __align__(16) float g_y[NN * DIM];   // y = A_hat @ x

// ------------------------- init: zero counters + dtype detection -------------
__global__ void k_init(const int* __restrict__ ei32) {
    int i = blockIdx.x * blockDim.x + threadIdx.x;
    if (i < NN) g_cnt[i] = 0;
    if (blockIdx.x == 0) {
        __shared__ int s_nz;
        if (threadIdx.x == 0) s_nz = 0;
        __syncthreads();
        for (int t = threadIdx.x; t < 8192; t += 256)
            if (ei32[2 * t + 1] != 0) s_nz = 1;   // racy store OK
        __syncthreads();
        if (threadIdx.x == 0) g_i64 = (s_nz == 0) ? 1 : 0;
    }
}

// ------------------ edge pass: bucketed fill, 2 edges/thread -----------------
__global__ void k_fill(const void* __restrict__ ei) {
    int q = blockIdx.x * blockDim.x + threadIdx.x;
    int e0 = q * 2;
    if (e0 >= NE) return;
    int s0, s1, d0, d1;
    if (!g_i64) {
        int2 sv = *(const int2*)((const int*)ei + e0);
        int2 dv = *(const int2*)((const int*)ei + NE + e0);
        s0 = sv.x; s1 = sv.y; d0 = dv.x; d1 = dv.y;
    } else {
        longlong2 sv = *(const longlong2*)((const long long*)ei + e0);
        longlong2 dv = *(const longlong2*)((const long long*)ei + NE + e0);
        s0 = (int)sv.x; s1 = (int)sv.y; d0 = (int)dv.x; d1 = (int)dv.y;
    }
    if ((unsigned)s0 < NN && (unsigned)d0 < NN) {
        int slot = atomicAdd(&g_cnt[d0], 1);
        if (slot < CAP) g_col[d0 * CAP + slot] = s0;
    }
    if ((unsigned)s1 < NN && (unsigned)d1 < NN) {
        int slot = atomicAdd(&g_cnt[d1], 1);
        if (slot < CAP) g_col[d1 * CAP + slot] = s1;
    }
}

// ------------------- cnt -> dinv, and xs = dinv * x (pre-scale) --------------
__global__ void k_pre(const float* __restrict__ x) {
    int t = blockIdx.x * blockDim.x + threadIdx.x;
    int node = t >> 4;
    if (node >= NN) return;
    int lane = t & 15;

    int d = g_cnt[node];
    float dd = rsqrtf(1.0f + (float)d);   // +1 self loop
    if (lane == 0) g_dinv[node] = dd;

    float4 v = ((const float4*)x)[(unsigned)node * 16 + lane];
    v.x *= dd; v.y *= dd; v.z *= dd; v.w *= dd;
    ((float4*)g_xs)[(unsigned)node * 16 + lane] = v;
}

// -------------------- f32x2 helpers (for k_agg) -------------------------------
__device__ __forceinline__ unsigned long long dup2(float v) {
    unsigned long long r;
    asm("mov.b64 %0, {%1, %1};" : "=l"(r) : "f"(v));
    return r;
}
__device__ __forceinline__ void add2(unsigned long long& acc, unsigned long long v) {
    asm("add.rn.f32x2 %0, %0, %1;" : "+l"(acc) : "l"(v));
}
__device__ __forceinline__ void mul2(unsigned long long& acc, unsigned long long v) {
    asm("mul.rn.f32x2 %0, %0, %1;" : "+l"(acc) : "l"(v));
}

// ---------- gather aggregation: y[d] = dinv[d]*(xs[d] + sum xs[s]) -----------
__global__ void k_agg() {
    int t = blockIdx.x * blockDim.x + threadIdx.x;
    int node = t >> 4;
    if (node >= NN) return;
    int lane = t & 15;

    const ulonglong2* xs2 = (const ulonglong2*)g_xs;
    ulonglong2 self = xs2[(unsigned)node * 16 + lane];
    unsigned long long a01 = self.x, a23 = self.y;
    unsigned long long b01 = dup2(0.f), b23 = dup2(0.f);

    int n = g_cnt[node];
    if (n > CAP) n = CAP;
    const int* col = g_col + node * CAP;

    int e = 0;
    for (; e + 4 <= n; e += 4) {
        int4 c = *(const int4*)(col + e);
        ulonglong2 v0 = xs2[(unsigned)c.x * 16 + lane];
        ulonglong2 v1 = xs2[(unsigned)c.y * 16 + lane];
        ulonglong2 v2 = xs2[(unsigned)c.z * 16 + lane];
        ulonglong2 v3 = xs2[(unsigned)c.w * 16 + lane];
        add2(a01, v0.x); add2(a23, v0.y);
        add2(b01, v1.x); add2(b23, v1.y);
        add2(a01, v2.x); add2(a23, v2.y);
        add2(b01, v3.x); add2(b23, v3.y);
    }
    for (; e < n; e++) {
        int s = col[e];
        ulonglong2 v = xs2[(unsigned)s * 16 + lane];
        add2(a01, v.x); add2(a23, v.y);
    }
    add2(a01, b01); add2(a23, b23);

    unsigned long long d2 = dup2(g_dinv[node]);
    mul2(a01, d2); mul2(a23, d2);

    ulonglong2 o; o.x = a01; o.y = a23;
    ((ulonglong2*)g_y)[(unsigned)node * 16 + lane] = o;
}

// ========== tensor-core epilogue: out = sum_k relu(y W_k + b_k) ==============
// Split-fp16 (Markidis): y = yhi+ylo, W = whi+wlo; acc = yhi*whi + yhi*wlo + ylo*whi
// in fp32 wmma accumulate. Error ~ (2^-11)^2, negligible.
// 256 threads = 8 warps; warp w: row-tile (w&3), col-tiles {(w>>2)*2, (w>>2)*2+1}.
__global__ void __launch_bounds__(256) k_gemm_tc(const float* __restrict__ W,
                                                 const float* __restrict__ b,
                                                 float* __restrict__ out) {
    __shared__ __align__(16) __half yhi[TR * DIM];       // 8 KB
    __shared__ __align__(16) __half ylo[TR * DIM];       // 8 KB
    __shared__ __align__(16) __half whi[DIM * DIM];      // 8 KB
    __shared__ __align__(16) __half wlo[DIM * DIM];      // 8 KB
    __shared__ __align__(16) float  bmat[16 * DIM];      // 4 KB (16 identical rows)
    __shared__ __align__(16) float  stg[8][16 * 16];     // 8 KB staging

    int tid  = threadIdx.x;
    int w    = tid >> 5;
    int lane = tid & 31;
    int rw   = w & 3;              // row tile 0..3
    int c0   = (w >> 2) * 2;       // first of 2 col tiles
    int row0 = blockIdx.x * TR;

    // ---- stage y split (rows row0..row0+63, zero-padded past NN) ------------
    for (int i = tid; i < TR * DIM; i += 256) {
        int node = row0 + (i >> 6);
        float v = (node < NN) ? g_y[(unsigned)node * DIM + (i & 63)] : 0.f;
        __half hi = __float2half_rn(v);
        yhi[i] = hi;
        ylo[i] = __float2half_rn(v - __half2float(hi));
    }

    wmma::fragment<wmma::accumulator, 16, 16, 16, float> of[2], cf;
#pragma unroll
    for (int t2 = 0; t2 < 2; t2++) wmma::fill_fragment(of[t2], 0.f);

    for (int k = 0; k < NK; k++) {
        __syncthreads();   // protect whi/wlo/bmat reuse + (k=0) y staging
        for (int i = tid; i < DIM * DIM; i += 256) {
            float v = W[k * DIM * DIM + i];
            __half hi = __float2half_rn(v);
            whi[i] = hi;
            wlo[i] = __float2half_rn(v - __half2float(hi));
        }
        for (int i = tid; i < 16 * DIM; i += 256)
            bmat[i] = b[k * DIM + (i & 63)];
        __syncthreads();

#pragma unroll
        for (int t2 = 0; t2 < 2; t2++) {
            int ct = c0 + t2;
            wmma::load_matrix_sync(cf, &bmat[ct * 16], DIM, wmma::mem_row_major);
#pragma unroll
            for (int kk = 0; kk < DIM / 16; kk++) {
                wmma::fragment<wmma::matrix_a, 16, 16, 16, __half, wmma::row_major> ah, al;
                wmma::fragment<wmma::matrix_b, 16, 16, 16, __half, wmma::row_major> bh, bl;
                wmma::load_matrix_sync(ah, &yhi[(rw * 16) * DIM + kk * 16], DIM);
                wmma::load_matrix_sync(al, &ylo[(rw * 16) * DIM + kk * 16], DIM);
                wmma::load_matrix_sync(bh, &whi[(kk * 16) * DIM + ct * 16], DIM);
                wmma::load_matrix_sync(bl, &wlo[(kk * 16) * DIM + ct * 16], DIM);
                wmma::mma_sync(cf, ah, bh, cf);
                wmma::mma_sync(cf, ah, bl, cf);
                wmma::mma_sync(cf, al, bh, cf);
            }
#pragma unroll
            for (int i = 0; i < cf.num_elements; i++)
                of[t2].x[i] += fmaxf(cf.x[i], 0.f);
        }
    }

    // ---- store via staging with row guard -----------------------------------
#pragma unroll
    for (int t2 = 0; t2 < 2; t2++) {
        int ct = c0 + t2;
        wmma::store_matrix_sync(&stg[w][0], of[t2], 16, wmma::mem_row_major);
        __syncwarp();
        if (lane < 16) {
            int r = row0 + rw * 16 + lane;
            if (r < NN) {
                const float4* src = (const float4*)&stg[w][lane * 16];
                float4* dst = (float4*)(out + (unsigned)r * DIM + ct * 16);
                dst[0] = src[0]; dst[1] = src[1]; dst[2] = src[2]; dst[3] = src[3];
            }
        }
        __syncwarp();
    }
}

// ----------------------------------------------------------------- launch ----
extern "C" void kernel_launch(void* const* d_in, const int* in_sizes, int n_in,
                              void* d_out, int out_size) {
    const float* x  = (const float*)d_in[0];
    const void*  ei = d_in[1];
    const float* W  = (const float*)d_in[2];
    const float* b  = (const float*)d_in[3];
    float* out = (float*)d_out;

    k_init    <<<(NN + 255) / 256, 256>>>((const int*)ei);
    k_fill    <<<(NE / 2 + 255) / 256, 256>>>(ei);
    k_pre     <<<(NN * 16 + 255) / 256, 256>>>(x);
    k_agg     <<<(NN * 16 + 255) / 256, 256>>>();
    k_gemm_tc <<<(NN + TR - 1) / TR, 256>>>(W, b, out);
}

// round 16
// speedup vs baseline: 1.7230x; 1.7230x over previous
#include <cuda_runtime.h>

#define NN 50000
#define NE 800000
#define DIM 64
#define NK 3
#define TR 128   // rows per GEMM block
#define CAP 64   // per-node bucket capacity (max in-degree ~45 for Poisson(16))

// ---- static scratch (no allocation allowed) ----
__device__ int   g_i64;
__device__ int   g_cnt[NN];
__device__ __align__(16) int g_col[NN * CAP];
__device__ float g_dinv[NN];
__device__ __align__(16) float g_xs[NN * DIM];
__device__ __align__(16) float g_y[NN * DIM];

// ------------------------- init: zero counters + dtype detection -------------
__global__ void k_init(const int* __restrict__ ei32) {
    int i = blockIdx.x * blockDim.x + threadIdx.x;
    if (i < NN) g_cnt[i] = 0;
    if (blockIdx.x == 0) {
        __shared__ int s_nz;
        if (threadIdx.x == 0) s_nz = 0;
        __syncthreads();
        for (int t = threadIdx.x; t < 8192; t += 256)
            if (ei32[2 * t + 1] != 0) s_nz = 1;   // racy store OK
        __syncthreads();
        if (threadIdx.x == 0) g_i64 = (s_nz == 0) ? 1 : 0;
    }
}

// ------------------ edge pass: bucketed fill, 2 edges/thread -----------------
__global__ void k_fill(const void* __restrict__ ei) {
    int q = blockIdx.x * blockDim.x + threadIdx.x;
    int e0 = q * 2;
    if (e0 >= NE) return;
    int s0, s1, d0, d1;
    if (!g_i64) {
        int2 sv = *(const int2*)((const int*)ei + e0);
        int2 dv = *(const int2*)((const int*)ei + NE + e0);
        s0 = sv.x; s1 = sv.y; d0 = dv.x; d1 = dv.y;
    } else {
        longlong2 sv = *(const longlong2*)((const long long*)ei + e0);
        longlong2 dv = *(const longlong2*)((const long long*)ei + NE + e0);
        s0 = (int)sv.x; s1 = (int)sv.y; d0 = (int)dv.x; d1 = (int)dv.y;
    }
    if ((unsigned)s0 < NN && (unsigned)d0 < NN) {
        int slot = atomicAdd(&g_cnt[d0], 1);
        if (slot < CAP) g_col[d0 * CAP + slot] = s0;
    }
    if ((unsigned)s1 < NN && (unsigned)d1 < NN) {
        int slot = atomicAdd(&g_cnt[d1], 1);
        if (slot < CAP) g_col[d1 * CAP + slot] = s1;
    }
}

// ------------------- cnt -> dinv, and xs = dinv * x (pre-scale) --------------
__global__ void k_pre(const float* __restrict__ x) {
    int t = blockIdx.x * blockDim.x + threadIdx.x;
    int node = t >> 4;
    if (node >= NN) return;
    int lane = t & 15;
    int d = g_cnt[node];
    float dd = rsqrtf(1.0f + (float)d);
    if (lane == 0) g_dinv[node] = dd;
    float4 v = ((const float4*)x)[(unsigned)node * 16 + lane];
    v.x *= dd; v.y *= dd; v.z *= dd; v.w *= dd;
    ((float4*)g_xs)[(unsigned)node * 16 + lane] = v;
}

// -------------------- f32x2 helpers ------------------------------------------
__device__ __forceinline__ unsigned long long pack2(float lo, float hi) {
    unsigned long long r;
    asm("mov.b64 %0, {%1, %2};" : "=l"(r) : "f"(lo), "f"(hi));
    return r;
}
__device__ __forceinline__ unsigned long long dup2(float v) {
    unsigned long long r;
    asm("mov.b64 %0, {%1, %1};" : "=l"(r) : "f"(v));
    return r;
}
__device__ __forceinline__ void fma2(unsigned long long& acc,
                                     unsigned long long a, unsigned long long b) {
    asm("fma.rn.f32x2 %0, %1, %2, %0;" : "+l"(acc) : "l"(a), "l"(b));
}
__device__ __forceinline__ void add2(unsigned long long& acc, unsigned long long v) {
    asm("add.rn.f32x2 %0, %0, %1;" : "+l"(acc) : "l"(v));
}
__device__ __forceinline__ void mul2(unsigned long long& acc, unsigned long long v) {
    asm("mul.rn.f32x2 %0, %0, %1;" : "+l"(acc) : "l"(v));
}
__device__ __forceinline__ void unpack2(unsigned long long v, float& lo, float& hi) {
    asm("mov.b64 {%0, %1}, %2;" : "=f"(lo), "=f"(hi) : "l"(v));
}

// ---------- gather aggregation: y[d] = dinv[d]*(xs[d] + sum xs[s]) -----------
__global__ void k_agg() {
    int t = blockIdx.x * blockDim.x + threadIdx.x;
    int node = t >> 4;
    if (node >= NN) return;
    int lane = t & 15;

    const ulonglong2* xs2 = (const ulonglong2*)g_xs;
    ulonglong2 self = xs2[(unsigned)node * 16 + lane];
    unsigned long long a01 = self.x, a23 = self.y;
    unsigned long long b01 = dup2(0.f), b23 = dup2(0.f);

    int n = g_cnt[node];
    if (n > CAP) n = CAP;
    const int* col = g_col + node * CAP;

    int e = 0;
    for (; e + 4 <= n; e += 4) {
        int4 c = *(const int4*)(col + e);
        ulonglong2 v0 = xs2[(unsigned)c.x * 16 + lane];
        ulonglong2 v1 = xs2[(unsigned)c.y * 16 + lane];
        ulonglong2 v2 = xs2[(unsigned)c.z * 16 + lane];
        ulonglong2 v3 = xs2[(unsigned)c.w * 16 + lane];
        add2(a01, v0.x); add2(a23, v0.y);
        add2(b01, v1.x); add2(b23, v1.y);
        add2(a01, v2.x); add2(a23, v2.y);
        add2(b01, v3.x); add2(b23, v3.y);
    }
    for (; e < n; e++) {
        int s = col[e];
        ulonglong2 v = xs2[(unsigned)s * 16 + lane];
        add2(a01, v.x); add2(a23, v.y);
    }
    add2(a01, b01); add2(a23, b23);

    unsigned long long d2 = dup2(g_dinv[node]);
    mul2(a01, d2); mul2(a23, d2);

    ulonglong2 o; o.x = a01; o.y = a23;
    ((ulonglong2*)g_y)[(unsigned)node * 16 + lane] = o;
}

// ---------------- fused epilogue with packed f32x2 FMA ------------------------
// 256 threads, 128x64 tile. Thread: cols {4cq..4cq+3} as two f32x2 packs,
// rows {rg+16m, m=0..7}. 8-row blocking halves per-MAC issue overhead.
__global__ void __launch_bounds__(256) k_gemm(const float* __restrict__ W,
                                              const float* __restrict__ b,
                                              float* __restrict__ out) {
    __shared__ __align__(16) float ws[DIM * DIM];     // [j][c], 16 KB
    __shared__ __align__(16) float ys[TR * DIM];      // [r][j], 32 KB

    int tid = threadIdx.x;
    int cq = tid & 15;           // column quad
    int rg = tid >> 4;           // 0..15
    int row0 = blockIdx.x * TR;

    // stage y tile (128 rows x 16 float4)
    {
        const float4* ysrc = (const float4*)g_y;
        float4* ydst = (float4*)ys;
        int base = row0 * (DIM / 4);
        for (int i = tid; i < TR * DIM / 4; i += 256) {
            if (base + i < NN * (DIM / 4)) ydst[i] = ysrc[base + i];
        }
    }

    float accR[8][4];
#pragma unroll
    for (int m = 0; m < 8; m++)
#pragma unroll
        for (int c = 0; c < 4; c++) accR[m][c] = 0.f;

    for (int k = 0; k < NK; k++) {
        __syncthreads();   // covers ys staging (k=0) and prior ws reads (k>0)
        {
            const float4* wsrc = (const float4*)(W + k * DIM * DIM);
            float4* wdst = (float4*)ws;
#pragma unroll
            for (int i = 0; i < 4; i++)
                wdst[tid + i * 256] = wsrc[tid + i * 256];
        }
        __syncthreads();

        const float* bk = b + k * DIM + cq * 4;
        unsigned long long a01[8], a23[8];
        {
            unsigned long long bb01 = pack2(bk[0], bk[1]);
            unsigned long long bb23 = pack2(bk[2], bk[3]);
#pragma unroll
            for (int m = 0; m < 8; m++) { a01[m] = bb01; a23[m] = bb23; }
        }

        const ulonglong2* wsu = (const ulonglong2*)ws;
#pragma unroll
        for (int j0 = 0; j0 < DIM; j0 += 4) {
            float4 yv[8];
#pragma unroll
            for (int m = 0; m < 8; m++)
                yv[m] = *(const float4*)&ys[(rg + 16 * m) * DIM + j0];
#pragma unroll
            for (int jj = 0; jj < 4; jj++) {
                ulonglong2 wv = wsu[(j0 + jj) * 16 + cq];
#pragma unroll
                for (int m = 0; m < 8; m++) {
                    float yf = ((const float*)&yv[m])[jj];
                    unsigned long long y2 = dup2(yf);
                    fma2(a01[m], y2, wv.x);
                    fma2(a23[m], y2, wv.y);
                }
            }
        }
#pragma unroll
        for (int m = 0; m < 8; m++) {
            float f0, f1, f2, f3;
            unpack2(a01[m], f0, f1);
            unpack2(a23[m], f2, f3);
            accR[m][0] += fmaxf(f0, 0.f);
            accR[m][1] += fmaxf(f1, 0.f);
            accR[m][2] += fmaxf(f2, 0.f);
            accR[m][3] += fmaxf(f3, 0.f);
        }
    }

#pragma unroll
    for (int m = 0; m < 8; m++) {
        int r = row0 + rg + m * 16;
        if (r < NN) {
            float4 o;
            o.x = accR[m][0]; o.y = accR[m][1];
            o.z = accR[m][2]; o.w = accR[m][3];
            ((float4*)out)[(unsigned)r * 16 + cq] = o;
        }
    }
}

// ----------------------------------------------------------------- launch ----
extern "C" void kernel_launch(void* const* d_in, const int* in_sizes, int n_in,
                              void* d_out, int out_size) {
    const float* x  = (const float*)d_in[0];
    const void*  ei = d_in[1];
    const float* W  = (const float*)d_in[2];
    const float* b  = (const float*)d_in[3];
    float* out = (float*)d_out;

    k_init <<<(NN + 255) / 256, 256>>>((const int*)ei);
    k_fill <<<(NE / 2 + 255) / 256, 256>>>(ei);
    k_pre  <<<(NN * 16 + 255) / 256, 256>>>(x);
    k_agg  <<<(NN * 16 + 255) / 256, 256>>>();
    k_gemm <<<(NN + TR - 1) / TR, 256>>>(W, b, out);
}